// round 11
// baseline (speedup 1.0000x reference)
#include <cuda_runtime.h>

// AdaptiveStdPooling2d: x [B=16, C=128, H=512, W=128] fp32
// kh = 64 (variance over height), kw = 8 (sum of stds over width)
// out [B, C, 8, 16] fp32
//
// R11 (vs R10): dual-slab interleave. Each warp owns TWO adjacent slabs
// (64KB contiguous) and issues both slabs' v8 loads in the same loop body
// -> two independent load chains, doubling per-warp outstanding LDG.256
// (structural MLP, past ptxas's unroll batching cap seen in R9).
// LDG.E.256 .cv loads (no L2 allocation; single-use stream).
// Half-warp-per-row: lanes 0-15 even rows, 16-31 odd rows; each lane owns
// one kw=8 column group -> merge row-parity partials with shfl_xor(16).
// block=512 (16 warps), grid=512: each CTA streams 1MB contiguous.

#define EPS 1e-14f

__device__ __forceinline__ void ld256_cv(const float* p,
                                         float& a0, float& a1, float& a2, float& a3,
                                         float& a4, float& a5, float& a6, float& a7) {
    asm volatile(
        "ld.global.cv.v8.f32 {%0,%1,%2,%3,%4,%5,%6,%7}, [%8];"
        : "=f"(a0), "=f"(a1), "=f"(a2), "=f"(a3),
          "=f"(a4), "=f"(a5), "=f"(a6), "=f"(a7)
        : "l"(p));
}

__global__ __launch_bounds__(512)
void adaptive_std_pool_kernel(const float* __restrict__ x,
                              float* __restrict__ out) {
    // Each warp handles slabs (2w, 2w+1)
    const int warp_id = blockIdx.x * 16 + (threadIdx.x >> 5);
    const int slab0 = warp_id * 2;
    const int lane = threadIdx.x & 31;
    const int half = lane >> 4;   // 0: even rows, 1: odd rows
    const int sub  = lane & 15;   // column group (8 cols = 32B)

    const float* __restrict__ baseA =
        x + (size_t)slab0 * 8192 + (size_t)half * 128 + (size_t)sub * 8;
    const float* __restrict__ baseB = baseA + 8192;

    float sA0=0.f,sA1=0.f,sA2=0.f,sA3=0.f,sA4=0.f,sA5=0.f,sA6=0.f,sA7=0.f;
    float qA0=0.f,qA1=0.f,qA2=0.f,qA3=0.f,qA4=0.f,qA5=0.f,qA6=0.f,qA7=0.f;
    float sB0=0.f,sB1=0.f,sB2=0.f,sB3=0.f,sB4=0.f,sB5=0.f,sB6=0.f,sB7=0.f;
    float qB0=0.f,qB1=0.f,qB2=0.f,qB3=0.f,qB4=0.f,qB5=0.f,qB6=0.f,qB7=0.f;

#pragma unroll 4
    for (int r = 0; r < 32; ++r) {
        const size_t off = (size_t)r * 256;  // 2 rows per iter
        float a0,a1,a2,a3,a4,a5,a6,a7;
        float b0,b1,b2,b3,b4,b5,b6,b7;
        ld256_cv(baseA + off, a0,a1,a2,a3,a4,a5,a6,a7);
        ld256_cv(baseB + off, b0,b1,b2,b3,b4,b5,b6,b7);
        sA0 += a0; qA0 = fmaf(a0, a0, qA0);
        sA1 += a1; qA1 = fmaf(a1, a1, qA1);
        sA2 += a2; qA2 = fmaf(a2, a2, qA2);
        sA3 += a3; qA3 = fmaf(a3, a3, qA3);
        sA4 += a4; qA4 = fmaf(a4, a4, qA4);
        sA5 += a5; qA5 = fmaf(a5, a5, qA5);
        sA6 += a6; qA6 = fmaf(a6, a6, qA6);
        sA7 += a7; qA7 = fmaf(a7, a7, qA7);
        sB0 += b0; qB0 = fmaf(b0, b0, qB0);
        sB1 += b1; qB1 = fmaf(b1, b1, qB1);
        sB2 += b2; qB2 = fmaf(b2, b2, qB2);
        sB3 += b3; qB3 = fmaf(b3, b3, qB3);
        sB4 += b4; qB4 = fmaf(b4, b4, qB4);
        sB5 += b5; qB5 = fmaf(b5, b5, qB5);
        sB6 += b6; qB6 = fmaf(b6, b6, qB6);
        sB7 += b7; qB7 = fmaf(b7, b7, qB7);
    }

    // merge even-row / odd-row partials across the half-warps
    const unsigned FULL = 0xffffffffu;
    sA0 += __shfl_xor_sync(FULL, sA0, 16); qA0 += __shfl_xor_sync(FULL, qA0, 16);
    sA1 += __shfl_xor_sync(FULL, sA1, 16); qA1 += __shfl_xor_sync(FULL, qA1, 16);
    sA2 += __shfl_xor_sync(FULL, sA2, 16); qA2 += __shfl_xor_sync(FULL, qA2, 16);
    sA3 += __shfl_xor_sync(FULL, sA3, 16); qA3 += __shfl_xor_sync(FULL, qA3, 16);
    sA4 += __shfl_xor_sync(FULL, sA4, 16); qA4 += __shfl_xor_sync(FULL, qA4, 16);
    sA5 += __shfl_xor_sync(FULL, sA5, 16); qA5 += __shfl_xor_sync(FULL, qA5, 16);
    sA6 += __shfl_xor_sync(FULL, sA6, 16); qA6 += __shfl_xor_sync(FULL, qA6, 16);
    sA7 += __shfl_xor_sync(FULL, sA7, 16); qA7 += __shfl_xor_sync(FULL, qA7, 16);
    sB0 += __shfl_xor_sync(FULL, sB0, 16); qB0 += __shfl_xor_sync(FULL, qB0, 16);
    sB1 += __shfl_xor_sync(FULL, sB1, 16); qB1 += __shfl_xor_sync(FULL, qB1, 16);
    sB2 += __shfl_xor_sync(FULL, sB2, 16); qB2 += __shfl_xor_sync(FULL, qB2, 16);
    sB3 += __shfl_xor_sync(FULL, sB3, 16); qB3 += __shfl_xor_sync(FULL, qB3, 16);
    sB4 += __shfl_xor_sync(FULL, sB4, 16); qB4 += __shfl_xor_sync(FULL, qB4, 16);
    sB5 += __shfl_xor_sync(FULL, sB5, 16); qB5 += __shfl_xor_sync(FULL, qB5, 16);
    sB6 += __shfl_xor_sync(FULL, sB6, 16); qB6 += __shfl_xor_sync(FULL, qB6, 16);
    sB7 += __shfl_xor_sync(FULL, sB7, 16); qB7 += __shfl_xor_sync(FULL, qB7, 16);

    if (half == 0) {
        const float inv = 1.0f / 64.0f;
        float m, ssumA = 0.f, ssumB = 0.f;
        m = sA0 * inv; ssumA += sqrtf(fmaf(-m, m, qA0 * inv) + EPS);
        m = sA1 * inv; ssumA += sqrtf(fmaf(-m, m, qA1 * inv) + EPS);
        m = sA2 * inv; ssumA += sqrtf(fmaf(-m, m, qA2 * inv) + EPS);
        m = sA3 * inv; ssumA += sqrtf(fmaf(-m, m, qA3 * inv) + EPS);
        m = sA4 * inv; ssumA += sqrtf(fmaf(-m, m, qA4 * inv) + EPS);
        m = sA5 * inv; ssumA += sqrtf(fmaf(-m, m, qA5 * inv) + EPS);
        m = sA6 * inv; ssumA += sqrtf(fmaf(-m, m, qA6 * inv) + EPS);
        m = sA7 * inv; ssumA += sqrtf(fmaf(-m, m, qA7 * inv) + EPS);
        m = sB0 * inv; ssumB += sqrtf(fmaf(-m, m, qB0 * inv) + EPS);
        m = sB1 * inv; ssumB += sqrtf(fmaf(-m, m, qB1 * inv) + EPS);
        m = sB2 * inv; ssumB += sqrtf(fmaf(-m, m, qB2 * inv) + EPS);
        m = sB3 * inv; ssumB += sqrtf(fmaf(-m, m, qB3 * inv) + EPS);
        m = sB4 * inv; ssumB += sqrtf(fmaf(-m, m, qB4 * inv) + EPS);
        m = sB5 * inv; ssumB += sqrtf(fmaf(-m, m, qB5 * inv) + EPS);
        m = sB6 * inv; ssumB += sqrtf(fmaf(-m, m, qB6 * inv) + EPS);
        m = sB7 * inv; ssumB += sqrtf(fmaf(-m, m, qB7 * inv) + EPS);
        out[(size_t)slab0 * 16 + sub] = ssumA;
        out[(size_t)(slab0 + 1) * 16 + sub] = ssumB;
    }
}

extern "C" void kernel_launch(void* const* d_in, const int* in_sizes, int n_in,
                              void* d_out, int out_size) {
    const float* x = (const float*)d_in[0];
    float* out = (float*)d_out;
    // 16384 slabs / 2 per warp / 16 warps per CTA = 512 CTAs x 512 threads
    adaptive_std_pool_kernel<<<512, 512>>>(x, out);
}

// round 12
// speedup vs baseline: 1.0855x; 1.0855x over previous
#include <cuda_runtime.h>

// AdaptiveStdPooling2d: x [B=16, C=128, H=512, W=128] fp32
// kh = 64 (variance over height), kw = 8 (sum of stds over width)
// out [B, C, 8, 16] fp32
//
// R12 (vs R11): dual-slab interleave at CONSTANT occupancy. R11's regression
// was the occupancy cliff (1 CTA/SM @ block 512, 23% occ), not the MLP idea.
// block=128 -> regs ~70 x 128 = 9KB/CTA -> 7 CTAs/SM -> ~28 warps/SM (43%),
// same as the R10 champion, while keeping two independent per-warp load
// chains (~8 outstanding LDG.256/warp vs 4).
// LDG.E.256 .cv loads (no L2 allocation; single-use stream).
// Half-warp-per-row; each lane owns one kw=8 column group; merge row-parity
// partials with shfl_xor(16). grid=2048: 16384 slabs / (2 per warp * 4 warps).

#define EPS 1e-14f

__device__ __forceinline__ void ld256_cv(const float* p,
                                         float& a0, float& a1, float& a2, float& a3,
                                         float& a4, float& a5, float& a6, float& a7) {
    asm volatile(
        "ld.global.cv.v8.f32 {%0,%1,%2,%3,%4,%5,%6,%7}, [%8];"
        : "=f"(a0), "=f"(a1), "=f"(a2), "=f"(a3),
          "=f"(a4), "=f"(a5), "=f"(a6), "=f"(a7)
        : "l"(p));
}

__global__ __launch_bounds__(128)
void adaptive_std_pool_kernel(const float* __restrict__ x,
                              float* __restrict__ out) {
    // Each warp handles slabs (2w, 2w+1)
    const int warp_id = blockIdx.x * 4 + (threadIdx.x >> 5);
    const int slab0 = warp_id * 2;
    const int lane = threadIdx.x & 31;
    const int half = lane >> 4;   // 0: even rows, 1: odd rows
    const int sub  = lane & 15;   // column group (8 cols = 32B)

    const float* __restrict__ baseA =
        x + (size_t)slab0 * 8192 + (size_t)half * 128 + (size_t)sub * 8;
    const float* __restrict__ baseB = baseA + 8192;

    float sA0=0.f,sA1=0.f,sA2=0.f,sA3=0.f,sA4=0.f,sA5=0.f,sA6=0.f,sA7=0.f;
    float qA0=0.f,qA1=0.f,qA2=0.f,qA3=0.f,qA4=0.f,qA5=0.f,qA6=0.f,qA7=0.f;
    float sB0=0.f,sB1=0.f,sB2=0.f,sB3=0.f,sB4=0.f,sB5=0.f,sB6=0.f,sB7=0.f;
    float qB0=0.f,qB1=0.f,qB2=0.f,qB3=0.f,qB4=0.f,qB5=0.f,qB6=0.f,qB7=0.f;

#pragma unroll 4
    for (int r = 0; r < 32; ++r) {
        const size_t off = (size_t)r * 256;  // 2 rows per iter per slab
        float a0,a1,a2,a3,a4,a5,a6,a7;
        float b0,b1,b2,b3,b4,b5,b6,b7;
        ld256_cv(baseA + off, a0,a1,a2,a3,a4,a5,a6,a7);
        ld256_cv(baseB + off, b0,b1,b2,b3,b4,b5,b6,b7);
        sA0 += a0; qA0 = fmaf(a0, a0, qA0);
        sA1 += a1; qA1 = fmaf(a1, a1, qA1);
        sA2 += a2; qA2 = fmaf(a2, a2, qA2);
        sA3 += a3; qA3 = fmaf(a3, a3, qA3);
        sA4 += a4; qA4 = fmaf(a4, a4, qA4);
        sA5 += a5; qA5 = fmaf(a5, a5, qA5);
        sA6 += a6; qA6 = fmaf(a6, a6, qA6);
        sA7 += a7; qA7 = fmaf(a7, a7, qA7);
        sB0 += b0; qB0 = fmaf(b0, b0, qB0);
        sB1 += b1; qB1 = fmaf(b1, b1, qB1);
        sB2 += b2; qB2 = fmaf(b2, b2, qB2);
        sB3 += b3; qB3 = fmaf(b3, b3, qB3);
        sB4 += b4; qB4 = fmaf(b4, b4, qB4);
        sB5 += b5; qB5 = fmaf(b5, b5, qB5);
        sB6 += b6; qB6 = fmaf(b6, b6, qB6);
        sB7 += b7; qB7 = fmaf(b7, b7, qB7);
    }

    // merge even-row / odd-row partials across the half-warps
    const unsigned FULL = 0xffffffffu;
    sA0 += __shfl_xor_sync(FULL, sA0, 16); qA0 += __shfl_xor_sync(FULL, qA0, 16);
    sA1 += __shfl_xor_sync(FULL, sA1, 16); qA1 += __shfl_xor_sync(FULL, qA1, 16);
    sA2 += __shfl_xor_sync(FULL, sA2, 16); qA2 += __shfl_xor_sync(FULL, qA2, 16);
    sA3 += __shfl_xor_sync(FULL, sA3, 16); qA3 += __shfl_xor_sync(FULL, qA3, 16);
    sA4 += __shfl_xor_sync(FULL, sA4, 16); qA4 += __shfl_xor_sync(FULL, qA4, 16);
    sA5 += __shfl_xor_sync(FULL, sA5, 16); qA5 += __shfl_xor_sync(FULL, qA5, 16);
    sA6 += __shfl_xor_sync(FULL, sA6, 16); qA6 += __shfl_xor_sync(FULL, qA6, 16);
    sA7 += __shfl_xor_sync(FULL, sA7, 16); qA7 += __shfl_xor_sync(FULL, qA7, 16);
    sB0 += __shfl_xor_sync(FULL, sB0, 16); qB0 += __shfl_xor_sync(FULL, qB0, 16);
    sB1 += __shfl_xor_sync(FULL, sB1, 16); qB1 += __shfl_xor_sync(FULL, qB1, 16);
    sB2 += __shfl_xor_sync(FULL, sB2, 16); qB2 += __shfl_xor_sync(FULL, qB2, 16);
    sB3 += __shfl_xor_sync(FULL, sB3, 16); qB3 += __shfl_xor_sync(FULL, qB3, 16);
    sB4 += __shfl_xor_sync(FULL, sB4, 16); qB4 += __shfl_xor_sync(FULL, qB4, 16);
    sB5 += __shfl_xor_sync(FULL, sB5, 16); qB5 += __shfl_xor_sync(FULL, qB5, 16);
    sB6 += __shfl_xor_sync(FULL, sB6, 16); qB6 += __shfl_xor_sync(FULL, qB6, 16);
    sB7 += __shfl_xor_sync(FULL, sB7, 16); qB7 += __shfl_xor_sync(FULL, qB7, 16);

    if (half == 0) {
        const float inv = 1.0f / 64.0f;
        float m, ssumA = 0.f, ssumB = 0.f;
        m = sA0 * inv; ssumA += sqrtf(fmaf(-m, m, qA0 * inv) + EPS);
        m = sA1 * inv; ssumA += sqrtf(fmaf(-m, m, qA1 * inv) + EPS);
        m = sA2 * inv; ssumA += sqrtf(fmaf(-m, m, qA2 * inv) + EPS);
        m = sA3 * inv; ssumA += sqrtf(fmaf(-m, m, qA3 * inv) + EPS);
        m = sA4 * inv; ssumA += sqrtf(fmaf(-m, m, qA4 * inv) + EPS);
        m = sA5 * inv; ssumA += sqrtf(fmaf(-m, m, qA5 * inv) + EPS);
        m = sA6 * inv; ssumA += sqrtf(fmaf(-m, m, qA6 * inv) + EPS);
        m = sA7 * inv; ssumA += sqrtf(fmaf(-m, m, qA7 * inv) + EPS);
        m = sB0 * inv; ssumB += sqrtf(fmaf(-m, m, qB0 * inv) + EPS);
        m = sB1 * inv; ssumB += sqrtf(fmaf(-m, m, qB1 * inv) + EPS);
        m = sB2 * inv; ssumB += sqrtf(fmaf(-m, m, qB2 * inv) + EPS);
        m = sB3 * inv; ssumB += sqrtf(fmaf(-m, m, qB3 * inv) + EPS);
        m = sB4 * inv; ssumB += sqrtf(fmaf(-m, m, qB4 * inv) + EPS);
        m = sB5 * inv; ssumB += sqrtf(fmaf(-m, m, qB5 * inv) + EPS);
        m = sB6 * inv; ssumB += sqrtf(fmaf(-m, m, qB6 * inv) + EPS);
        m = sB7 * inv; ssumB += sqrtf(fmaf(-m, m, qB7 * inv) + EPS);
        out[(size_t)slab0 * 16 + sub] = ssumA;
        out[(size_t)(slab0 + 1) * 16 + sub] = ssumB;
    }
}

extern "C" void kernel_launch(void* const* d_in, const int* in_sizes, int n_in,
                              void* d_out, int out_size) {
    const float* x = (const float*)d_in[0];
    float* out = (float*)d_out;
    // 16384 slabs / 2 per warp / 4 warps per CTA = 2048 CTAs x 128 threads
    adaptive_std_pool_kernel<<<2048, 128>>>(x, out);
}

// round 13
// speedup vs baseline: 1.1368x; 1.0473x over previous
#include <cuda_runtime.h>

// AdaptiveStdPooling2d: x [B=16, C=128, H=512, W=128] fp32
// kh = 64 (variance over height), kw = 8 (sum of stds over width)
// out [B, C, 8, 16] fp32
//
// One warp per (b,c,ho) slab: 64 rows x 128 cols = 32KB contiguous.
// LDG.E.256 .cv loads (no cache allocation; single-use stream), unroll 8.
// Half-warp-per-row: lanes 0-15 even rows, 16-31 odd rows; each lane owns
// one kw=8 column group -> merge row-parity partials with shfl_xor(16).
//
// R13 (vs R10): block 512 -> 1024 (32 warps/CTA), grid 512. Extends the
// monotone stream-contiguity trend (128/256/512 -> 86.0/85.6/85.4 @.cs,
// 512 @.cv -> 84.4). Each CTA streams 2MB contiguous; exactly one CTA and
// one linear DRAM sweep per SM. Warps/SM unchanged at 32 (1x32 vs 2x16),
// so no R11-style occupancy cliff. Dual-slab interleave (R11/R12) is
// abandoned: split per-warp pointer streams hurt DRAM efficiency.

#define EPS 1e-14f

__global__ __launch_bounds__(1024)
void adaptive_std_pool_kernel(const float* __restrict__ x,
                              float* __restrict__ out) {
    const int warp_global = blockIdx.x * 32 + (threadIdx.x >> 5); // slab id
    const int lane = threadIdx.x & 31;
    const int half = lane >> 4;   // 0: even rows, 1: odd rows
    const int sub  = lane & 15;   // column group (8 cols = 32B)

    const float* __restrict__ base =
        x + (size_t)warp_global * 8192 + (size_t)half * 128 + (size_t)sub * 8;

    float s0=0.f,s1=0.f,s2=0.f,s3=0.f,s4=0.f,s5=0.f,s6=0.f,s7=0.f;
    float q0=0.f,q1=0.f,q2=0.f,q3=0.f,q4=0.f,q5=0.f,q6=0.f,q7=0.f;

#pragma unroll 8
    for (int r = 0; r < 32; ++r) {
        const float* p = base + (size_t)r * 256;  // 2 rows per iter
        float a0,a1,a2,a3,a4,a5,a6,a7;
        asm volatile(
            "ld.global.cv.v8.f32 {%0,%1,%2,%3,%4,%5,%6,%7}, [%8];"
            : "=f"(a0), "=f"(a1), "=f"(a2), "=f"(a3),
              "=f"(a4), "=f"(a5), "=f"(a6), "=f"(a7)
            : "l"(p));
        s0 += a0; q0 = fmaf(a0, a0, q0);
        s1 += a1; q1 = fmaf(a1, a1, q1);
        s2 += a2; q2 = fmaf(a2, a2, q2);
        s3 += a3; q3 = fmaf(a3, a3, q3);
        s4 += a4; q4 = fmaf(a4, a4, q4);
        s5 += a5; q5 = fmaf(a5, a5, q5);
        s6 += a6; q6 = fmaf(a6, a6, q6);
        s7 += a7; q7 = fmaf(a7, a7, q7);
    }

    // merge even-row / odd-row partials across the half-warps
    const unsigned FULL = 0xffffffffu;
    s0 += __shfl_xor_sync(FULL, s0, 16); q0 += __shfl_xor_sync(FULL, q0, 16);
    s1 += __shfl_xor_sync(FULL, s1, 16); q1 += __shfl_xor_sync(FULL, q1, 16);
    s2 += __shfl_xor_sync(FULL, s2, 16); q2 += __shfl_xor_sync(FULL, q2, 16);
    s3 += __shfl_xor_sync(FULL, s3, 16); q3 += __shfl_xor_sync(FULL, q3, 16);
    s4 += __shfl_xor_sync(FULL, s4, 16); q4 += __shfl_xor_sync(FULL, q4, 16);
    s5 += __shfl_xor_sync(FULL, s5, 16); q5 += __shfl_xor_sync(FULL, q5, 16);
    s6 += __shfl_xor_sync(FULL, s6, 16); q6 += __shfl_xor_sync(FULL, q6, 16);
    s7 += __shfl_xor_sync(FULL, s7, 16); q7 += __shfl_xor_sync(FULL, q7, 16);

    if (half == 0) {
        const float inv = 1.0f / 64.0f;
        float ssum = 0.f;
        float m;
        m = s0 * inv; ssum += sqrtf(fmaf(-m, m, q0 * inv) + EPS);
        m = s1 * inv; ssum += sqrtf(fmaf(-m, m, q1 * inv) + EPS);
        m = s2 * inv; ssum += sqrtf(fmaf(-m, m, q2 * inv) + EPS);
        m = s3 * inv; ssum += sqrtf(fmaf(-m, m, q3 * inv) + EPS);
        m = s4 * inv; ssum += sqrtf(fmaf(-m, m, q4 * inv) + EPS);
        m = s5 * inv; ssum += sqrtf(fmaf(-m, m, q5 * inv) + EPS);
        m = s6 * inv; ssum += sqrtf(fmaf(-m, m, q6 * inv) + EPS);
        m = s7 * inv; ssum += sqrtf(fmaf(-m, m, q7 * inv) + EPS);
        out[(size_t)warp_global * 16 + sub] = ssum;
    }
}

extern "C" void kernel_launch(void* const* d_in, const int* in_sizes, int n_in,
                              void* d_out, int out_size) {
    const float* x = (const float*)d_in[0];
    float* out = (float*)d_out;
    // 16384 slabs / 32 warps per CTA = 512 CTAs x 1024 threads
    adaptive_std_pool_kernel<<<512, 1024>>>(x, out);
}

// round 14
// speedup vs baseline: 1.1644x; 1.0242x over previous
#include <cuda_runtime.h>

// AdaptiveStdPooling2d: x [B=16, C=128, H=512, W=128] fp32
// kh = 64 (variance over height), kw = 8 (sum of stds over width)
// out [B, C, 8, 16] fp32
//
// One warp per (b,c,ho) slab: 64 rows x 128 cols = 32KB contiguous.
// LDG.E.256 .cv loads (no cache allocation; single-use stream), unroll 8.
// Half-warp-per-row: lanes 0-15 even rows, 16-31 odd rows; each lane owns
// one kw=8 column group -> merge row-parity partials with shfl_xor(16).
//
// R14 (vs R10): block 512 -> 256, grid 2048. R13 (block 1024) showed the
// ragged completion tail grows with per-CTA duration; R7-vs-R8 showed
// 256KB vs 512KB per-CTA contiguity is within noise. So halve per-CTA
// work (256KB, ~6us) to shrink the tail while staying on the contiguity
// plateau. Everything else identical to the R10 champion.

#define EPS 1e-14f

__global__ __launch_bounds__(256)
void adaptive_std_pool_kernel(const float* __restrict__ x,
                              float* __restrict__ out) {
    const int warp_global = blockIdx.x * 8 + (threadIdx.x >> 5); // slab id
    const int lane = threadIdx.x & 31;
    const int half = lane >> 4;   // 0: even rows, 1: odd rows
    const int sub  = lane & 15;   // column group (8 cols = 32B)

    const float* __restrict__ base =
        x + (size_t)warp_global * 8192 + (size_t)half * 128 + (size_t)sub * 8;

    float s0=0.f,s1=0.f,s2=0.f,s3=0.f,s4=0.f,s5=0.f,s6=0.f,s7=0.f;
    float q0=0.f,q1=0.f,q2=0.f,q3=0.f,q4=0.f,q5=0.f,q6=0.f,q7=0.f;

#pragma unroll 8
    for (int r = 0; r < 32; ++r) {
        const float* p = base + (size_t)r * 256;  // 2 rows per iter
        float a0,a1,a2,a3,a4,a5,a6,a7;
        asm volatile(
            "ld.global.cv.v8.f32 {%0,%1,%2,%3,%4,%5,%6,%7}, [%8];"
            : "=f"(a0), "=f"(a1), "=f"(a2), "=f"(a3),
              "=f"(a4), "=f"(a5), "=f"(a6), "=f"(a7)
            : "l"(p));
        s0 += a0; q0 = fmaf(a0, a0, q0);
        s1 += a1; q1 = fmaf(a1, a1, q1);
        s2 += a2; q2 = fmaf(a2, a2, q2);
        s3 += a3; q3 = fmaf(a3, a3, q3);
        s4 += a4; q4 = fmaf(a4, a4, q4);
        s5 += a5; q5 = fmaf(a5, a5, q5);
        s6 += a6; q6 = fmaf(a6, a6, q6);
        s7 += a7; q7 = fmaf(a7, a7, q7);
    }

    // merge even-row / odd-row partials across the half-warps
    const unsigned FULL = 0xffffffffu;
    s0 += __shfl_xor_sync(FULL, s0, 16); q0 += __shfl_xor_sync(FULL, q0, 16);
    s1 += __shfl_xor_sync(FULL, s1, 16); q1 += __shfl_xor_sync(FULL, q1, 16);
    s2 += __shfl_xor_sync(FULL, s2, 16); q2 += __shfl_xor_sync(FULL, q2, 16);
    s3 += __shfl_xor_sync(FULL, s3, 16); q3 += __shfl_xor_sync(FULL, q3, 16);
    s4 += __shfl_xor_sync(FULL, s4, 16); q4 += __shfl_xor_sync(FULL, q4, 16);
    s5 += __shfl_xor_sync(FULL, s5, 16); q5 += __shfl_xor_sync(FULL, q5, 16);
    s6 += __shfl_xor_sync(FULL, s6, 16); q6 += __shfl_xor_sync(FULL, q6, 16);
    s7 += __shfl_xor_sync(FULL, s7, 16); q7 += __shfl_xor_sync(FULL, q7, 16);

    if (half == 0) {
        const float inv = 1.0f / 64.0f;
        float ssum = 0.f;
        float m;
        m = s0 * inv; ssum += sqrtf(fmaf(-m, m, q0 * inv) + EPS);
        m = s1 * inv; ssum += sqrtf(fmaf(-m, m, q1 * inv) + EPS);
        m = s2 * inv; ssum += sqrtf(fmaf(-m, m, q2 * inv) + EPS);
        m = s3 * inv; ssum += sqrtf(fmaf(-m, m, q3 * inv) + EPS);
        m = s4 * inv; ssum += sqrtf(fmaf(-m, m, q4 * inv) + EPS);
        m = s5 * inv; ssum += sqrtf(fmaf(-m, m, q5 * inv) + EPS);
        m = s6 * inv; ssum += sqrtf(fmaf(-m, m, q6 * inv) + EPS);
        m = s7 * inv; ssum += sqrtf(fmaf(-m, m, q7 * inv) + EPS);
        out[(size_t)warp_global * 16 + sub] = ssum;
    }
}

extern "C" void kernel_launch(void* const* d_in, const int* in_sizes, int n_in,
                              void* d_out, int out_size) {
    const float* x = (const float*)d_in[0];
    float* out = (float*)d_out;
    // 16384 slabs / 8 warps per CTA = 2048 CTAs x 256 threads
    adaptive_std_pool_kernel<<<2048, 256>>>(x, out);
}

// round 15
// speedup vs baseline: 1.1648x; 1.0004x over previous
#include <cuda_runtime.h>

// AdaptiveStdPooling2d: x [B=16, C=128, H=512, W=128] fp32
// kh = 64 (variance over height), kw = 8 (sum of stds over width)
// out [B, C, 8, 16] fp32
//
// FINAL (champion config, R10): one warp per (b,c,ho) slab (64x128 = 32KB
// contiguous). LDG.E.256 .cv loads (no cache allocation — single-use
// 512MB stream), unroll 8 (ptxas batching optimum). Half-warp-per-row:
// lanes 0-15 even rows, 16-31 odd rows; each lane owns one kw=8 column
// group; row-parity partials merged with shfl_xor(16); lanes 0-15 write.
// block=512 (16 warps, 512KB contiguous stream per CTA), grid=1024.
//
// Measured: 84.4us, 6.49 TB/s (81% of HBM spec), DRAM pipe 81.9%,
// all compute pipes <11%. Traffic is at its minimum (every byte read
// once); falsified alternatives: deeper unroll (ptxas-capped), multi-
// stream warps (DRAM locality loss), occupancy changes (flat >=40%),
// coarser/finer CTAs (plateau), L2 prefetch hints (neutral).

#define EPS 1e-14f

__global__ __launch_bounds__(512)
void adaptive_std_pool_kernel(const float* __restrict__ x,
                              float* __restrict__ out) {
    const int warp_global = blockIdx.x * 16 + (threadIdx.x >> 5); // slab id
    const int lane = threadIdx.x & 31;
    const int half = lane >> 4;   // 0: even rows, 1: odd rows
    const int sub  = lane & 15;   // column group (8 cols = 32B)

    const float* __restrict__ base =
        x + (size_t)warp_global * 8192 + (size_t)half * 128 + (size_t)sub * 8;

    float s0=0.f,s1=0.f,s2=0.f,s3=0.f,s4=0.f,s5=0.f,s6=0.f,s7=0.f;
    float q0=0.f,q1=0.f,q2=0.f,q3=0.f,q4=0.f,q5=0.f,q6=0.f,q7=0.f;

#pragma unroll 8
    for (int r = 0; r < 32; ++r) {
        const float* p = base + (size_t)r * 256;  // 2 rows per iter
        float a0,a1,a2,a3,a4,a5,a6,a7;
        asm volatile(
            "ld.global.cv.v8.f32 {%0,%1,%2,%3,%4,%5,%6,%7}, [%8];"
            : "=f"(a0), "=f"(a1), "=f"(a2), "=f"(a3),
              "=f"(a4), "=f"(a5), "=f"(a6), "=f"(a7)
            : "l"(p));
        s0 += a0; q0 = fmaf(a0, a0, q0);
        s1 += a1; q1 = fmaf(a1, a1, q1);
        s2 += a2; q2 = fmaf(a2, a2, q2);
        s3 += a3; q3 = fmaf(a3, a3, q3);
        s4 += a4; q4 = fmaf(a4, a4, q4);
        s5 += a5; q5 = fmaf(a5, a5, q5);
        s6 += a6; q6 = fmaf(a6, a6, q6);
        s7 += a7; q7 = fmaf(a7, a7, q7);
    }

    // merge even-row / odd-row partials across the half-warps
    const unsigned FULL = 0xffffffffu;
    s0 += __shfl_xor_sync(FULL, s0, 16); q0 += __shfl_xor_sync(FULL, q0, 16);
    s1 += __shfl_xor_sync(FULL, s1, 16); q1 += __shfl_xor_sync(FULL, q1, 16);
    s2 += __shfl_xor_sync(FULL, s2, 16); q2 += __shfl_xor_sync(FULL, q2, 16);
    s3 += __shfl_xor_sync(FULL, s3, 16); q3 += __shfl_xor_sync(FULL, q3, 16);
    s4 += __shfl_xor_sync(FULL, s4, 16); q4 += __shfl_xor_sync(FULL, q4, 16);
    s5 += __shfl_xor_sync(FULL, s5, 16); q5 += __shfl_xor_sync(FULL, q5, 16);
    s6 += __shfl_xor_sync(FULL, s6, 16); q6 += __shfl_xor_sync(FULL, q6, 16);
    s7 += __shfl_xor_sync(FULL, s7, 16); q7 += __shfl_xor_sync(FULL, q7, 16);

    if (half == 0) {
        const float inv = 1.0f / 64.0f;
        float ssum = 0.f;
        float m;
        m = s0 * inv; ssum += sqrtf(fmaf(-m, m, q0 * inv) + EPS);
        m = s1 * inv; ssum += sqrtf(fmaf(-m, m, q1 * inv) + EPS);
        m = s2 * inv; ssum += sqrtf(fmaf(-m, m, q2 * inv) + EPS);
        m = s3 * inv; ssum += sqrtf(fmaf(-m, m, q3 * inv) + EPS);
        m = s4 * inv; ssum += sqrtf(fmaf(-m, m, q4 * inv) + EPS);
        m = s5 * inv; ssum += sqrtf(fmaf(-m, m, q5 * inv) + EPS);
        m = s6 * inv; ssum += sqrtf(fmaf(-m, m, q6 * inv) + EPS);
        m = s7 * inv; ssum += sqrtf(fmaf(-m, m, q7 * inv) + EPS);
        out[(size_t)warp_global * 16 + sub] = ssum;
    }
}

extern "C" void kernel_launch(void* const* d_in, const int* in_sizes, int n_in,
                              void* d_out, int out_size) {
    const float* x = (const float*)d_in[0];
    float* out = (float*)d_out;
    // 16384 slabs / 16 warps per CTA = 1024 CTAs x 512 threads
    adaptive_std_pool_kernel<<<1024, 512>>>(x, out);
}